// round 12
// baseline (speedup 1.0000x reference)
#include <cuda_runtime.h>
#include <cuda_bf16.h>
#include <math.h>

#define NB   16
#define CC   4
#define HH   256
#define WW   256
#define TOT  (NB*CC*HH*WW)        // 4194304
#define NWORDS (TOT/32)           // 131072
#define FINF 1e10f
#define WT   8
#define KB_THREADS 512
#define KB_BLOCKS  (NB*(WW/WT))   // 512

// dynamic smem layout for kB
#define SM_MASK_BYTES (4*256*9*4)             // 36864
#define SM_SF_OFF     SM_MASK_BYTES           // 36864
#define SM_RED_OFF    (SM_SF_OFF + 4*256*9*4) // 73728
#define SM_TOTAL      (SM_RED_OFF + 2*KB_THREADS*4)  // 77824

// Scratch (static device arrays — no allocation)
__device__ unsigned int g_mask[NWORDS];   // seed bitmask, bit order = w
__device__ float g_pnum[KB_BLOCKS];
__device__ float g_pden[KB_BLOCKS];
__device__ int   g_cnt = 0;

// ---------------------------------------------------------------------------
// kA: build seed bitmask (seed = target!=0). One thread/element, ballot pack.
// ---------------------------------------------------------------------------
__global__ void kA_mask(const int* __restrict__ target,
                        unsigned int* __restrict__ mask) {
    int gid = blockIdx.x * 256 + threadIdx.x;
    int v = target[gid];
    unsigned int bal = __ballot_sync(0xFFFFFFFFu, v != 0);
    if ((threadIdx.x & 31) == 0) mask[gid >> 5] = bal;
}

// ---------------------------------------------------------------------------
// kB: per block (n, w-tile of 8):
//   1. load image-n bitmask into smem (rows padded to 9 words)
//   2. W nearest-set-bit distance per voxel (clz/ffs word scan, exact)
//   3. H-axis exact expanding-window min-plus + C min-plus + softmax + reduce
//   4. fused final reduction via atomic counter (last block writes out)
// ---------------------------------------------------------------------------
extern __shared__ unsigned char s_raw[];

__global__ __launch_bounds__(KB_THREADS)
void kB_main(const unsigned int* __restrict__ mask,
             const float* __restrict__ pred,
             float* __restrict__ out) {
    unsigned int* smask = (unsigned int*)s_raw;
    float* sf   = (float*)(s_raw + SM_SF_OFF);
    float* snum = (float*)(s_raw + SM_RED_OFF);
    float* sden = snum + KB_THREADS;
    __shared__ bool isLast;

    const int n     = blockIdx.x >> 5;
    const int w0    = (blockIdx.x & 31) * WT;
    const int t     = threadIdx.x;
    const int nbase = n << 18;           // n*CHW
    const int mbase = n << 13;           // n*8192 words

    // ---- phase 1: load masks (coalesced), pad rows to 9 ----
#pragma unroll
    for (int j = 0; j < 16; ++j) {
        int e   = t + (j << 9);          // 0..8191 = (c*256+h)*8 + wd
        int row = e >> 3;
        int wd  = e & 7;
        smask[row * 9 + wd] = mask[mbase + e];
    }
    __syncthreads();

    // ---- phase 2: W nearest-seed distance^2 per voxel ----
#pragma unroll 2
    for (int j = 0; j < 16; ++j) {
        int e   = t + (j << 9);
        int row = e >> 3;                // c*256+h
        int wp  = e & 7;
        int w   = w0 + wp;
        int wi  = w >> 5;
        int bpos = w & 31;
        const unsigned int* mrow = &smask[row * 9];
        unsigned int own = mrow[wi];

        int dd = 1 << 20, du = 1 << 20;
        unsigned int m = own & (0xFFFFFFFFu >> (31 - bpos));
        if (m) {
            dd = bpos - (31 - __clz(m));
        } else {
            for (int q = wi - 1; q >= 0; --q) {
                unsigned int wq = mrow[q];
                if (wq) { dd = bpos + ((wi - q) << 5) - (31 - __clz(wq)); break; }
            }
        }
        m = own & (0xFFFFFFFFu << bpos);
        if (m) {
            du = (__ffs(m) - 1) - bpos;
        } else {
            for (int q = wi + 1; q < 8; ++q) {
                unsigned int wq = mrow[q];
                if (wq) { du = ((q << 5) + (__ffs(wq) - 1)) - w; break; }
            }
        }
        int r = dd < du ? dd : du;
        sf[row * 9 + wp] = (r >= 65536) ? FINF : (float)(r * r);
    }
    __syncthreads();

    // ---- phase 3: H-search + C min-plus + softmax + accumulate ----
    float num = 0.0f, den = 0.0f;
#pragma unroll
    for (int j = 0; j < 4; ++j) {
        int e  = t + (j << 9);           // 0..2047
        int wp = e & 7;
        int h  = e >> 3;

        float d[CC];
#pragma unroll
        for (int c = 0; c < CC; ++c) {
            const float* col = &sf[c * 2304 + wp];   // (c*256)*9 + wp
            float mm = col[h * 9];
            if (mm > 1.0f) {
                int rlo = h;
                int rhi = 255 - h;
                int rmax = rlo > rhi ? rlo : rhi;
                for (int r = 1; r <= rmax; ++r) {
                    float r2 = (float)(r * r);
                    if (r2 >= mm) break;
                    if (r <= rlo) mm = fminf(mm, col[(h - r) * 9] + r2);
                    if (r <= rhi) mm = fminf(mm, col[(h + r) * 9] + r2);
                }
            }
            d[c] = mm;
        }

        float m0 = fminf(fminf(d[0], d[1] + 1.0f), fminf(d[2] + 4.0f, d[3] + 9.0f));
        float m1 = fminf(fminf(d[1], fminf(d[0], d[2]) + 1.0f), d[3] + 4.0f);
        float m2 = fminf(fminf(d[2], fminf(d[1], d[3]) + 1.0f), d[0] + 4.0f);
        float m3 = fminf(fminf(d[3], d[2] + 1.0f), fminf(d[1] + 4.0f, d[0] + 9.0f));

        float d0 = sqrtf(m0);
        float d1 = sqrtf(m1);
        float d2 = sqrtf(m2);
        float d3 = sqrtf(m3);

        int pbase = nbase + (h << 8) + w0 + wp;
        float p0 = pred[pbase];
        float p1 = pred[pbase + (1 << 16)];
        float p2 = pred[pbase + (2 << 16)];
        float p3 = pred[pbase + (3 << 16)];
        float mx = fmaxf(fmaxf(p0, p1), fmaxf(p2, p3));
        float e0 = __expf(p0 - mx);
        float e1 = __expf(p1 - mx);
        float e2 = __expf(p2 - mx);
        float e3 = __expf(p3 - mx);
        float s  = e0 + e1 + e2 + e3;
        num += __fdividef(e0 * d0 + e1 * d1 + e2 * d2 + e3 * d3, s);
        den += d0 + d1 + d2 + d3;
    }

    // ---- phase 4: block reduction + fused final ----
    snum[t] = num;
    sden[t] = den;
    __syncthreads();
#pragma unroll
    for (int off = 256; off > 0; off >>= 1) {
        if (t < off) {
            snum[t] += snum[t + off];
            sden[t] += sden[t + off];
        }
        __syncthreads();
    }
    if (t == 0) {
        g_pnum[blockIdx.x] = snum[0];
        g_pden[blockIdx.x] = sden[0];
        __threadfence();
        int prev = atomicAdd(&g_cnt, 1);
        isLast = (prev == KB_BLOCKS - 1);
    }
    __syncthreads();

    if (isLast) {
        double* dnum = (double*)s_raw;           // reuse mask region
        double* dden = dnum + KB_THREADS;
        dnum[t] = (double)g_pnum[t];             // KB_BLOCKS == KB_THREADS == 512
        dden[t] = (double)g_pden[t];
        __syncthreads();
#pragma unroll
        for (int off = 256; off > 0; off >>= 1) {
            if (t < off) {
                dnum[t] += dnum[t + off];
                dden[t] += dden[t + off];
            }
            __syncthreads();
        }
        if (t == 0) {
            out[0] = (float)(dnum[0] / (dden[0] + 1e-10));
            g_cnt = 0;                           // reset for next replay
        }
    }
}

// ---------------------------------------------------------------------------
extern "C" void kernel_launch(void* const* d_in, const int* in_sizes, int n_in,
                              void* d_out, int out_size) {
    const float* pred   = (const float*)d_in[0];
    const int*   target = (const int*)d_in[1];
    float* out = (float*)d_out;

    unsigned int* mask;
    cudaGetSymbolAddress((void**)&mask, g_mask);

    cudaFuncSetAttribute(kB_main, cudaFuncAttributeMaxDynamicSharedMemorySize,
                         SM_TOTAL);

    kA_mask<<<TOT / 256, 256>>>(target, mask);
    kB_main<<<KB_BLOCKS, KB_THREADS, SM_TOTAL>>>(mask, pred, out);
}

// round 13
// speedup vs baseline: 2.0326x; 2.0326x over previous
#include <cuda_runtime.h>
#include <cuda_bf16.h>
#include <math.h>

#define NB   16
#define CC   4
#define HH   256
#define WW   256
#define CHW  (CC*HH*WW)           // 262144
#define TOT  (NB*CHW)             // 4194304
#define NROWS (NB*CC*HH)          // 16384 rows of 256 w
#define FINF 1e10f
#define WT   8
#define KB_BLOCKS (NB*(WW/WT))    // 512

// Scratch (static device arrays — no allocation)
__device__ unsigned short g_rw[TOT];   // nearest-seed radius along W (0xFFFF = none)
__device__ float g_pnum[KB_BLOCKS];
__device__ float g_pden[KB_BLOCKS];

// ---------------------------------------------------------------------------
// kW: W-axis nearest-seed radius, one warp per row, all-register bitmask.
// Warp loads 256 targets (8 coalesced loads), ballots into 8 words that every
// lane holds in registers. Lane l handles columns w = l + 32*j  (bpos = l,
// word index = j), so the lo/hi masks are loop-invariant and wv[] indexing is
// static under full unroll. Exact nearest set bit via clz/ffs + word scan.
// ---------------------------------------------------------------------------
__global__ void kW(const int* __restrict__ target,
                   unsigned short* __restrict__ rw) {
    const int warp = threadIdx.x >> 5;
    const int lane = threadIdx.x & 31;
    const int row  = (blockIdx.x << 3) + warp;   // 0..16383
    const int gbase = row << 8;

    unsigned int wv[8];
#pragma unroll
    for (int q = 0; q < 8; ++q) {
        int v = target[gbase + (q << 5) + lane];
        wv[q] = __ballot_sync(0xFFFFFFFFu, v != 0);
    }

    const unsigned int maskLo = 0xFFFFFFFFu >> (31 - lane);  // bits <= lane
    const unsigned int maskHi = 0xFFFFFFFFu << lane;         // bits >= lane

#pragma unroll
    for (int j = 0; j < 8; ++j) {
        const unsigned int own = wv[j];
        int dd = 1 << 20, du = 1 << 20;

        unsigned int m = own & maskLo;
        if (m) {
            dd = lane - (31 - __clz(m));
        } else {
#pragma unroll
            for (int q = j - 1; q >= 0; --q) {
                if (wv[q]) { dd = lane + ((j - q) << 5) - (31 - __clz(wv[q])); break; }
            }
        }
        m = own & maskHi;
        if (m) {
            du = (__ffs(m) - 1) - lane;
        } else {
#pragma unroll
            for (int q = j + 1; q < 8; ++q) {
                if (wv[q]) { du = ((q - j) << 5) + (__ffs(wv[q]) - 1) - lane; break; }
            }
        }
        int r = dd < du ? dd : du;
        rw[gbase + (j << 5) + lane] = (r >= 0xFFFF) ? (unsigned short)0xFFFF
                                                    : (unsigned short)r;
    }
}

// ---------------------------------------------------------------------------
// kB: fused H-pass (exact expanding-window min-plus) + C min-plus + softmax +
// block reduction. Block = (n, w-tile of 8), 512 threads.
// smem sf padded to row stride 9 (bank-conflict-free column walks).
// ---------------------------------------------------------------------------
__global__ void __launch_bounds__(512)
kB_hcred(const unsigned short* __restrict__ rw,
         const float* __restrict__ pred) {
    __shared__ float sf[4 * 256 * 9];     // (c*256+h)*9 + wp
    __shared__ float snum[512];
    __shared__ float sden[512];

    const int n  = blockIdx.x >> 5;
    const int w0 = (blockIdx.x & 31) * WT;
    const int t  = threadIdx.x;
    const int nbase = n << 18;

    // ---- load + decode rw tile (uint4 = 8 u16 per (c,h) row) ----
#pragma unroll
    for (int i = 0; i < 2; ++i) {
        int e = t + (i << 9);             // 0..1023: c = e>>8, h = e&255
        int c = e >> 8;
        int h = e & 255;
        uint4 v = *(const uint4*)(rw + nbase + (c << 16) + (h << 8) + w0);
        float* dst = &sf[e * 9];
        unsigned r0 = v.x & 0xFFFFu, r1 = v.x >> 16;
        unsigned r2 = v.y & 0xFFFFu, r3 = v.y >> 16;
        unsigned r4 = v.z & 0xFFFFu, r5 = v.z >> 16;
        unsigned r6 = v.w & 0xFFFFu, r7 = v.w >> 16;
        dst[0] = (r0 == 0xFFFFu) ? FINF : (float)(r0 * r0);
        dst[1] = (r1 == 0xFFFFu) ? FINF : (float)(r1 * r1);
        dst[2] = (r2 == 0xFFFFu) ? FINF : (float)(r2 * r2);
        dst[3] = (r3 == 0xFFFFu) ? FINF : (float)(r3 * r3);
        dst[4] = (r4 == 0xFFFFu) ? FINF : (float)(r4 * r4);
        dst[5] = (r5 == 0xFFFFu) ? FINF : (float)(r5 * r5);
        dst[6] = (r6 == 0xFFFFu) ? FINF : (float)(r6 * r6);
        dst[7] = (r7 == 0xFFFFu) ? FINF : (float)(r7 * r7);
    }
    __syncthreads();

    // ---- per voxel: H-search (exact), C min-plus, softmax, accumulate ----
    float num = 0.0f, den = 0.0f;
#pragma unroll
    for (int i = 0; i < 4; ++i) {
        int e  = t + (i << 9);            // 0..2047: wp = e&7, h = e>>3
        int wp = e & 7;
        int h  = e >> 3;

        float d[CC];
#pragma unroll
        for (int c = 0; c < CC; ++c) {
            const float* col = &sf[c * 2304 + wp];   // (c*256)*9 + wp
            float mm = col[h * 9];
            if (mm > 1.0f) {
                int rlo = h;
                int rhi = 255 - h;
                int rmax = rlo > rhi ? rlo : rhi;
                for (int r = 1; r <= rmax; ++r) {
                    float r2 = (float)(r * r);
                    if (r2 >= mm) break;
                    if (r <= rlo) mm = fminf(mm, col[(h - r) * 9] + r2);
                    if (r <= rhi) mm = fminf(mm, col[(h + r) * 9] + r2);
                }
            }
            d[c] = mm;
        }

        // C-axis min-plus (exact, length 4)
        float m0 = fminf(fminf(d[0], d[1] + 1.0f), fminf(d[2] + 4.0f, d[3] + 9.0f));
        float m1 = fminf(fminf(d[1], fminf(d[0], d[2]) + 1.0f), d[3] + 4.0f);
        float m2 = fminf(fminf(d[2], fminf(d[1], d[3]) + 1.0f), d[0] + 4.0f);
        float m3 = fminf(fminf(d[3], d[2] + 1.0f), fminf(d[1] + 4.0f, d[0] + 9.0f));

        float d0 = sqrtf(m0);
        float d1 = sqrtf(m1);
        float d2 = sqrtf(m2);
        float d3 = sqrtf(m3);

        int pbase = nbase + (h << 8) + w0 + wp;
        float p0 = pred[pbase];
        float p1 = pred[pbase + (1 << 16)];
        float p2 = pred[pbase + (2 << 16)];
        float p3 = pred[pbase + (3 << 16)];
        float mx = fmaxf(fmaxf(p0, p1), fmaxf(p2, p3));
        float e0 = __expf(p0 - mx);
        float e1 = __expf(p1 - mx);
        float e2 = __expf(p2 - mx);
        float e3 = __expf(p3 - mx);
        float s  = e0 + e1 + e2 + e3;
        num += __fdividef(e0 * d0 + e1 * d1 + e2 * d2 + e3 * d3, s);
        den += d0 + d1 + d2 + d3;
    }

    // ---- block reduction (512) ----
    snum[t] = num;
    sden[t] = den;
    __syncthreads();
#pragma unroll
    for (int off = 256; off > 0; off >>= 1) {
        if (t < off) {
            snum[t] += snum[t + off];
            sden[t] += sden[t + off];
        }
        __syncthreads();
    }
    if (t == 0) {
        g_pnum[blockIdx.x] = snum[0];
        g_pden[blockIdx.x] = sden[0];
    }
}

// ---------------------------------------------------------------------------
// k3: final reduction over 512 block partials
// ---------------------------------------------------------------------------
__global__ void k3_final(float* __restrict__ out) {
    __shared__ double dnum[256];
    __shared__ double dden[256];
    int t = threadIdx.x;
    dnum[t] = (double)g_pnum[t] + (double)g_pnum[t + 256];
    dden[t] = (double)g_pden[t] + (double)g_pden[t + 256];
    __syncthreads();
#pragma unroll
    for (int off = 128; off > 0; off >>= 1) {
        if (t < off) {
            dnum[t] += dnum[t + off];
            dden[t] += dden[t + off];
        }
        __syncthreads();
    }
    if (t == 0)
        out[0] = (float)(dnum[0] / (dden[0] + 1e-10));
}

// ---------------------------------------------------------------------------
extern "C" void kernel_launch(void* const* d_in, const int* in_sizes, int n_in,
                              void* d_out, int out_size) {
    const float* pred   = (const float*)d_in[0];
    const int*   target = (const int*)d_in[1];
    float* out = (float*)d_out;

    unsigned short* rw;
    cudaGetSymbolAddress((void**)&rw, g_rw);

    kW      <<<NROWS / 8, 256>>>(target, rw);
    kB_hcred<<<KB_BLOCKS, 512>>>(rw, pred);
    k3_final<<<1,         256>>>(out);
}

// round 14
// speedup vs baseline: 2.1869x; 1.0759x over previous
#include <cuda_runtime.h>
#include <cuda_bf16.h>
#include <math.h>

#define NB   16
#define CC   4
#define HH   256
#define WW   256
#define CHW  (CC*HH*WW)           // 262144
#define TOT  (NB*CHW)             // 4194304
#define NROWS (NB*CC*HH)          // 16384 rows of 256 w
#define WT   8
#define KB_BLOCKS (NB*(WW/WT))    // 512
#define KB_THREADS 512

// Scratch (static device arrays — no allocation)
// g_rwt layout: [n][tile=w>>3 (32)][c (4)][h (256)][wp (8)]  (u8 radius)
__device__ unsigned char g_rwt[TOT];
__device__ float g_pnum[KB_BLOCKS];
__device__ float g_pden[KB_BLOCKS];
__device__ int   g_cnt = 0;

// ---------------------------------------------------------------------------
// kW: W-axis nearest-seed radius, one warp per (n,c,h) row, register bitmask.
// Warp ballots the row into 8 words held by every lane; lane l computes
// columns w = l + 32j (bpos = l -> masks loop-invariant, wv[] static index).
// Radius <= 255 whenever the row has any seed, so u8 is exact; output is
// scattered into the kB-tiled layout so kB reads are contiguous.
// ---------------------------------------------------------------------------
__global__ void kW(const int* __restrict__ target,
                   unsigned char* __restrict__ rwt) {
    const int warp = threadIdx.x >> 5;
    const int lane = threadIdx.x & 31;
    const int row  = (blockIdx.x << 3) + warp;   // n*1024 + c*256 + h
    const int gbase = row << 8;
    const int n  = row >> 10;
    const int ch = row & 1023;                   // c*256 + h

    unsigned int wv[8];
#pragma unroll
    for (int q = 0; q < 8; ++q) {
        int v = target[gbase + (q << 5) + lane];
        wv[q] = __ballot_sync(0xFFFFFFFFu, v != 0);
    }

    const unsigned int maskLo = 0xFFFFFFFFu >> (31 - lane);  // bits <= lane
    const unsigned int maskHi = 0xFFFFFFFFu << lane;         // bits >= lane

    // out addr = n*262144 + tile*8192 + ch*8 + wp ; tile = (lane>>3) + 4j
    unsigned char* obase = rwt + (n << 18) + ((lane >> 3) << 13) + (ch << 3)
                               + (lane & 7);

#pragma unroll
    for (int j = 0; j < 8; ++j) {
        const unsigned int own = wv[j];
        int dd = 1 << 20, du = 1 << 20;

        unsigned int m = own & maskLo;
        if (m) {
            dd = lane - (31 - __clz(m));
        } else {
#pragma unroll
            for (int q = j - 1; q >= 0; --q) {
                if (wv[q]) { dd = lane + ((j - q) << 5) - (31 - __clz(wv[q])); break; }
            }
        }
        m = own & maskHi;
        if (m) {
            du = (__ffs(m) - 1) - lane;
        } else {
#pragma unroll
            for (int q = j + 1; q < 8; ++q) {
                if (wv[q]) { du = ((q - j) << 5) + (__ffs(wv[q]) - 1) - lane; break; }
            }
        }
        int r = dd < du ? dd : du;
        if (r > 255) r = 255;
        obase[j << 15] = (unsigned char)r;       // 4j*8192 = j<<15
    }
}

// ---------------------------------------------------------------------------
// kB: fused H-pass (exact expanding-window min-plus) + C min-plus + softmax +
// block reduction + fused final reduction (last block).
// Block = (n, w-tile of 8), 512 threads. rw read is one contiguous 8KB slab.
// smem sf padded to row stride 9 (bank-conflict-light column walks).
// ---------------------------------------------------------------------------
__global__ void __launch_bounds__(KB_THREADS)
kB_main(const unsigned char* __restrict__ rwt,
        const float* __restrict__ pred,
        float* __restrict__ out) {
    __shared__ float sf[1024 * 9];       // (c*256+h)*9 + wp
    __shared__ float snum[KB_THREADS];
    __shared__ float sden[KB_THREADS];
    __shared__ bool isLast;

    const int n    = blockIdx.x >> 5;
    const int tile = blockIdx.x & 31;
    const int w0   = tile << 3;
    const int t    = threadIdx.x;
    const int nbase = n << 18;

    // ---- decode: one uint4 (16 voxels = 2 sf rows) per thread, coalesced ----
    {
        uint4 v = ((const uint4*)(rwt + nbase + (tile << 13)))[t];
        float* d0p = &sf[(2 * t) * 9];
        float* d1p = d0p + 9;
#define DEC8(wlo, whi, dst)                                                   \
        {                                                                     \
            unsigned a0 = (wlo) & 255u, a1 = ((wlo) >> 8) & 255u,             \
                     a2 = ((wlo) >> 16) & 255u, a3 = (wlo) >> 24;             \
            unsigned b0 = (whi) & 255u, b1 = ((whi) >> 8) & 255u,             \
                     b2 = ((whi) >> 16) & 255u, b3 = (whi) >> 24;             \
            dst[0] = (float)(a0 * a0); dst[1] = (float)(a1 * a1);             \
            dst[2] = (float)(a2 * a2); dst[3] = (float)(a3 * a3);             \
            dst[4] = (float)(b0 * b0); dst[5] = (float)(b1 * b1);             \
            dst[6] = (float)(b2 * b2); dst[7] = (float)(b3 * b3);             \
        }
        DEC8(v.x, v.y, d0p)
        DEC8(v.z, v.w, d1p)
#undef DEC8
    }
    __syncthreads();

    // ---- per pixel: H-search (exact), C min-plus, softmax, accumulate ----
    float num = 0.0f, den = 0.0f;
#pragma unroll
    for (int i = 0; i < 4; ++i) {
        int e  = t + (i << 9);            // 0..2047: wp = e&7, h = e>>3
        int wp = e & 7;
        int h  = e >> 3;

        float d[CC];
#pragma unroll
        for (int c = 0; c < CC; ++c) {
            const float* col = &sf[c * 2304 + wp];   // (c*256)*9 + wp
            float mm = col[h * 9];
            if (mm > 1.0f) {
                int rlo = h;
                int rhi = 255 - h;
                int rmax = rlo > rhi ? rlo : rhi;
                for (int r = 1; r <= rmax; ++r) {
                    float r2 = (float)(r * r);
                    if (r2 >= mm) break;
                    if (r <= rlo) mm = fminf(mm, col[(h - r) * 9] + r2);
                    if (r <= rhi) mm = fminf(mm, col[(h + r) * 9] + r2);
                }
            }
            d[c] = mm;
        }

        // C-axis min-plus (exact, length 4)
        float m0 = fminf(fminf(d[0], d[1] + 1.0f), fminf(d[2] + 4.0f, d[3] + 9.0f));
        float m1 = fminf(fminf(d[1], fminf(d[0], d[2]) + 1.0f), d[3] + 4.0f);
        float m2 = fminf(fminf(d[2], fminf(d[1], d[3]) + 1.0f), d[0] + 4.0f);
        float m3 = fminf(fminf(d[3], d[2] + 1.0f), fminf(d[1] + 4.0f, d[0] + 9.0f));

        // fast sqrt: m * rsqrt(m), exact-enough (~1e-6 rel), guard m==0
        float d0 = (m0 > 0.0f) ? m0 * rsqrtf(m0) : 0.0f;
        float d1 = (m1 > 0.0f) ? m1 * rsqrtf(m1) : 0.0f;
        float d2 = (m2 > 0.0f) ? m2 * rsqrtf(m2) : 0.0f;
        float d3 = (m3 > 0.0f) ? m3 * rsqrtf(m3) : 0.0f;

        int pbase = nbase + (h << 8) + w0 + wp;
        float p0 = pred[pbase];
        float p1 = pred[pbase + (1 << 16)];
        float p2 = pred[pbase + (2 << 16)];
        float p3 = pred[pbase + (3 << 16)];
        float mx = fmaxf(fmaxf(p0, p1), fmaxf(p2, p3));
        float e0 = __expf(p0 - mx);
        float e1 = __expf(p1 - mx);
        float e2 = __expf(p2 - mx);
        float e3 = __expf(p3 - mx);
        float s  = e0 + e1 + e2 + e3;
        num += __fdividef(e0 * d0 + e1 * d1 + e2 * d2 + e3 * d3, s);
        den += d0 + d1 + d2 + d3;
    }

    // ---- block reduction (512) ----
    snum[t] = num;
    sden[t] = den;
    __syncthreads();
#pragma unroll
    for (int off = 256; off > 0; off >>= 1) {
        if (t < off) {
            snum[t] += snum[t + off];
            sden[t] += sden[t + off];
        }
        __syncthreads();
    }
    if (t == 0) {
        g_pnum[blockIdx.x] = snum[0];
        g_pden[blockIdx.x] = sden[0];
        __threadfence();
        int prev = atomicAdd(&g_cnt, 1);
        isLast = (prev == KB_BLOCKS - 1);
    }
    __syncthreads();

    // ---- fused final reduction: last block sums 512 partials ----
    if (isLast) {
        double* dnum = (double*)sf;          // reuse sf (36KB >= 8KB)
        double* dden = dnum + KB_THREADS;
        dnum[t] = (double)g_pnum[t];         // KB_BLOCKS == KB_THREADS == 512
        dden[t] = (double)g_pden[t];
        __syncthreads();
#pragma unroll
        for (int off = 256; off > 0; off >>= 1) {
            if (t < off) {
                dnum[t] += dnum[t + off];
                dden[t] += dden[t + off];
            }
            __syncthreads();
        }
        if (t == 0) {
            out[0] = (float)(dnum[0] / (dden[0] + 1e-10));
            g_cnt = 0;                       // reset for next graph replay
        }
    }
}

// ---------------------------------------------------------------------------
extern "C" void kernel_launch(void* const* d_in, const int* in_sizes, int n_in,
                              void* d_out, int out_size) {
    const float* pred   = (const float*)d_in[0];
    const int*   target = (const int*)d_in[1];
    float* out = (float*)d_out;

    unsigned char* rwt;
    cudaGetSymbolAddress((void**)&rwt, g_rwt);

    kW     <<<NROWS / 8, 256>>>(target, rwt);
    kB_main<<<KB_BLOCKS, KB_THREADS>>>(rwt, pred, out);
}

// round 15
// speedup vs baseline: 2.2366x; 1.0227x over previous
#include <cuda_runtime.h>
#include <cuda_bf16.h>
#include <math.h>

#define NB   16
#define CC   4
#define HH   256
#define WW   256
#define CHW  (CC*HH*WW)           // 262144
#define TOT  (NB*CHW)             // 4194304
#define NROWS (NB*CC*HH)          // 16384 rows of 256 w
#define WT   8
#define KB_BLOCKS (NB*(WW/WT))    // 512
#define KB_THREADS 512
#define FINF 1e10f

// sf layout: per class 260 rows (2 pad + 256 + 2 pad), stride 9 floats
#define CLS_STRIDE (260*9)        // 2340
#define ROW0_OFF   (2*9)          // h=0 lives at row 2

// Scratch (static device arrays — no allocation)
// g_rwt layout: [n][tile=w>>3 (32)][c (4)][h (256)][wp (8)]  (u8 radius)
__device__ unsigned char g_rwt[TOT];
__device__ float g_pnum[KB_BLOCKS];
__device__ float g_pden[KB_BLOCKS];
__device__ int   g_cnt = 0;

// ---------------------------------------------------------------------------
// kW: W-axis nearest-seed radius, one warp per (n,c,h) row, register bitmask.
// (unchanged from R14 — ballot pack + clz/ffs nearest-bit, u8 tiled output)
// ---------------------------------------------------------------------------
__global__ void kW(const int* __restrict__ target,
                   unsigned char* __restrict__ rwt) {
    const int warp = threadIdx.x >> 5;
    const int lane = threadIdx.x & 31;
    const int row  = (blockIdx.x << 3) + warp;   // n*1024 + c*256 + h
    const int gbase = row << 8;
    const int n  = row >> 10;
    const int ch = row & 1023;                   // c*256 + h

    unsigned int wv[8];
#pragma unroll
    for (int q = 0; q < 8; ++q) {
        int v = target[gbase + (q << 5) + lane];
        wv[q] = __ballot_sync(0xFFFFFFFFu, v != 0);
    }

    const unsigned int maskLo = 0xFFFFFFFFu >> (31 - lane);
    const unsigned int maskHi = 0xFFFFFFFFu << lane;

    unsigned char* obase = rwt + (n << 18) + ((lane >> 3) << 13) + (ch << 3)
                               + (lane & 7);

#pragma unroll
    for (int j = 0; j < 8; ++j) {
        const unsigned int own = wv[j];
        int dd = 1 << 20, du = 1 << 20;

        unsigned int m = own & maskLo;
        if (m) {
            dd = lane - (31 - __clz(m));
        } else {
#pragma unroll
            for (int q = j - 1; q >= 0; --q) {
                if (wv[q]) { dd = lane + ((j - q) << 5) - (31 - __clz(wv[q])); break; }
            }
        }
        m = own & maskHi;
        if (m) {
            du = (__ffs(m) - 1) - lane;
        } else {
#pragma unroll
            for (int q = j + 1; q < 8; ++q) {
                if (wv[q]) { du = ((q - j) << 5) + (__ffs(wv[q]) - 1) - lane; break; }
            }
        }
        int r = dd < du ? dd : du;
        if (r > 255) r = 255;
        obase[j << 15] = (unsigned char)r;
    }
}

// ---------------------------------------------------------------------------
// kB: fused H-pass + C min-plus + softmax + reduction + fused final.
// H-pass: branchless r<=2 window (exact superset min) + ~never-taken exact
// fallback for r>=3 (only possible when m > 9). sf rows padded with 2 FINF
// rows per class end so the window needs no edge checks.
// ---------------------------------------------------------------------------
__global__ void __launch_bounds__(KB_THREADS)
kB_main(const unsigned char* __restrict__ rwt,
        const float* __restrict__ pred,
        float* __restrict__ out) {
    __shared__ float sf[CC * CLS_STRIDE];   // c*2340 + (h+2)*9 + wp
    __shared__ float snum[KB_THREADS];
    __shared__ float sden[KB_THREADS];
    __shared__ bool isLast;

    const int n    = blockIdx.x >> 5;
    const int tile = blockIdx.x & 31;
    const int w0   = tile << 3;
    const int t    = threadIdx.x;
    const int nbase = n << 18;

    // ---- fill pad rows (h = -2,-1,256,257 per class) with FINF ----
    if (t < 144) {                         // 4 c * 4 rows * 9 floats
        int c  = t / 36;
        int rem = t - c * 36;
        int pr = rem / 9;                  // 0..3
        int k  = rem - pr * 9;
        int prow = (pr < 2) ? pr : (254 + pr);   // 0,1,258,259
        sf[c * CLS_STRIDE + prow * 9 + k] = FINF;
    }

    // ---- decode: one uint4 (16 voxels = 2 rows) per thread, coalesced ----
    {
        uint4 v = ((const uint4*)(rwt + nbase + (tile << 13)))[t];
        int ch0 = 2 * t;                   // c*256+h
        int c   = ch0 >> 8;
        int h0  = ch0 & 255;
        float* d0p = &sf[c * CLS_STRIDE + (h0 + 2) * 9];
        float* d1p = d0p + 9;
#define DEC8(wlo, whi, dst)                                                   \
        {                                                                     \
            unsigned a0 = (wlo) & 255u, a1 = ((wlo) >> 8) & 255u,             \
                     a2 = ((wlo) >> 16) & 255u, a3 = (wlo) >> 24;             \
            unsigned b0 = (whi) & 255u, b1 = ((whi) >> 8) & 255u,             \
                     b2 = ((whi) >> 16) & 255u, b3 = (whi) >> 24;             \
            dst[0] = (float)(a0 * a0); dst[1] = (float)(a1 * a1);             \
            dst[2] = (float)(a2 * a2); dst[3] = (float)(a3 * a3);             \
            dst[4] = (float)(b0 * b0); dst[5] = (float)(b1 * b1);             \
            dst[6] = (float)(b2 * b2); dst[7] = (float)(b3 * b3);             \
        }
        DEC8(v.x, v.y, d0p)
        DEC8(v.z, v.w, d1p)
#undef DEC8
    }
    __syncthreads();

    // ---- per pixel: branchless H window, C min-plus, softmax, accumulate ----
    float num = 0.0f, den = 0.0f;
#pragma unroll
    for (int i = 0; i < 4; ++i) {
        int e  = t + (i << 9);            // 0..2047: wp = e&7, h = e>>3
        int wp = e & 7;
        int h  = e >> 3;

        float d[CC];
#pragma unroll
        for (int c = 0; c < CC; ++c) {
            const float* cp = &sf[c * CLS_STRIDE + (h + 2) * 9 + wp];
            float v0  = cp[0];
            float am1 = cp[-9],  ap1 = cp[9];
            float am2 = cp[-18], ap2 = cp[18];
            float m = fminf(v0,
                      fminf(fminf(am1, ap1) + 1.0f,
                            fminf(am2, ap2) + 4.0f));
            if (m > 9.0f) {               // ~1e-6 probability: exact fallback
                int rlo = h;
                int rhi = 255 - h;
                int rmax = rlo > rhi ? rlo : rhi;
                for (int r = 3; r <= rmax; ++r) {
                    float r2 = (float)(r * r);
                    if (r2 >= m) break;
                    if (r <= rlo) m = fminf(m, cp[-r * 9] + r2);
                    if (r <= rhi) m = fminf(m, cp[r * 9] + r2);
                }
            }
            d[c] = m;
        }

        // C-axis min-plus (exact, length 4)
        float m0 = fminf(fminf(d[0], d[1] + 1.0f), fminf(d[2] + 4.0f, d[3] + 9.0f));
        float m1 = fminf(fminf(d[1], fminf(d[0], d[2]) + 1.0f), d[3] + 4.0f);
        float m2 = fminf(fminf(d[2], fminf(d[1], d[3]) + 1.0f), d[0] + 4.0f);
        float m3 = fminf(fminf(d[3], d[2] + 1.0f), fminf(d[1] + 4.0f, d[0] + 9.0f));

        float d0 = (m0 > 0.0f) ? m0 * rsqrtf(m0) : 0.0f;
        float d1 = (m1 > 0.0f) ? m1 * rsqrtf(m1) : 0.0f;
        float d2 = (m2 > 0.0f) ? m2 * rsqrtf(m2) : 0.0f;
        float d3 = (m3 > 0.0f) ? m3 * rsqrtf(m3) : 0.0f;

        int pbase = nbase + (h << 8) + w0 + wp;
        float p0 = pred[pbase];
        float p1 = pred[pbase + (1 << 16)];
        float p2 = pred[pbase + (2 << 16)];
        float p3 = pred[pbase + (3 << 16)];
        float mx = fmaxf(fmaxf(p0, p1), fmaxf(p2, p3));
        float e0 = __expf(p0 - mx);
        float e1 = __expf(p1 - mx);
        float e2 = __expf(p2 - mx);
        float e3 = __expf(p3 - mx);
        float s  = e0 + e1 + e2 + e3;
        num += __fdividef(e0 * d0 + e1 * d1 + e2 * d2 + e3 * d3, s);
        den += d0 + d1 + d2 + d3;
    }

    // ---- block reduction (512) ----
    snum[t] = num;
    sden[t] = den;
    __syncthreads();
#pragma unroll
    for (int off = 256; off > 0; off >>= 1) {
        if (t < off) {
            snum[t] += snum[t + off];
            sden[t] += sden[t + off];
        }
        __syncthreads();
    }
    if (t == 0) {
        g_pnum[blockIdx.x] = snum[0];
        g_pden[blockIdx.x] = sden[0];
        __threadfence();
        int prev = atomicAdd(&g_cnt, 1);
        isLast = (prev == KB_BLOCKS - 1);
    }
    __syncthreads();

    // ---- fused final reduction: last block sums the 512 partials ----
    if (isLast) {
        double* dnum = (double*)sf;
        double* dden = dnum + KB_THREADS;
        dnum[t] = (double)g_pnum[t];       // KB_BLOCKS == KB_THREADS == 512
        dden[t] = (double)g_pden[t];
        __syncthreads();
#pragma unroll
        for (int off = 256; off > 0; off >>= 1) {
            if (t < off) {
                dnum[t] += dnum[t + off];
                dden[t] += dden[t + off];
            }
            __syncthreads();
        }
        if (t == 0) {
            out[0] = (float)(dnum[0] / (dden[0] + 1e-10));
            g_cnt = 0;                     // reset for next graph replay
        }
    }
}

// ---------------------------------------------------------------------------
extern "C" void kernel_launch(void* const* d_in, const int* in_sizes, int n_in,
                              void* d_out, int out_size) {
    const float* pred   = (const float*)d_in[0];
    const int*   target = (const int*)d_in[1];
    float* out = (float*)d_out;

    unsigned char* rwt;
    cudaGetSymbolAddress((void**)&rwt, g_rwt);

    kW     <<<NROWS / 8, 256>>>(target, rwt);
    kB_main<<<KB_BLOCKS, KB_THREADS>>>(rwt, pred, out);
}